// round 2
// baseline (speedup 1.0000x reference)
#include <cuda_runtime.h>
#include <math.h>

// Problem constants (fixed by the reference setup_inputs()).
namespace {
constexpr int T   = 16384;
constexpr int B   = 64;
constexpr int CIN = 8;
constexpr int H   = 32;   // hidden channels (layer 1 out)
constexpr int E   = 64;   // embed channels (layer 2 out)
constexpr int CH  = 512;  // time chunk per block
constexpr int W   = 64;   // LIF warm-up steps (0.5x decay/step + exact hard resets
                          //  -> chunk state re-converges to the true trajectory)
constexpr int NC  = T / CH;     // 32 chunks
constexpr int L   = CH + W + 2; // smem tile span: [ts-1, te]  (578)
}

// Layer-1 spikes as bitmasks: bit c of g_masks[b*T + t] = spike of channel c at t.
__device__ unsigned g_masks[B * T];

// ---------------------------------------------------------------------------
// Kernel A: conv1d(8->32,k=3,same) + BN(eval) + LIF  -> spike bitmasks.
// One warp per (batch, chunk); lane = output channel. Serial over t (warm-up +
// chunk); x tile staged in smem, x window register-rotated with period 4.
// ---------------------------------------------------------------------------
__global__ __launch_bounds__(32) void lif1_kernel(
    const float* __restrict__ x,  const float* __restrict__ w1,
    const float* __restrict__ b1, const float* __restrict__ g1,
    const float* __restrict__ be1, const float* __restrict__ m1,
    const float* __restrict__ v1) {
  __shared__ float xs[CIN][L];
  const int b    = blockIdx.y;
  const int t0   = blockIdx.x * CH;
  const int ts   = t0 - W;          // warm-up start (negative for chunk 0)
  const int te   = t0 + CH;
  const int base = ts - 1;          // xs[ci][j] = x[b,ci, base+j]
  const int lane = threadIdx.x;

  // Stage x tile (zero-pad outside [0,T) -> also the conv 'same' pads).
  for (int i = lane; i < CIN * L; i += 32) {
    int ci = i / L, j = i - ci * L;
    int g  = base + j;
    xs[ci][j] = (g >= 0 && g < T) ? x[(b * CIN + ci) * T + g] : 0.0f;
  }
  __syncwarp();

  // Per-lane weights + BN params (kept unfused to mirror reference algebra).
  float wa[CIN], wb[CIN], wc[CIN];
  const float* wp = w1 + lane * (CIN * 3);
#pragma unroll
  for (int ci = 0; ci < CIN; ci++) {
    wa[ci] = wp[ci * 3 + 0];
    wb[ci] = wp[ci * 3 + 1];
    wc[ci] = wp[ci * 3 + 2];
  }
  const float sc = g1[lane] / sqrtf(v1[lane] + 1e-5f);
  const float sh = be1[lane] - m1[lane] * sc;
  const float bb = b1[lane];

  float v = 0.0f;
  unsigned keep = 0;
  unsigned* mrow = g_masks + b * T;

  // Rotating x window: A=x(t-1), Bv=x(t), C<-x(t+1).
  float xA[CIN], xB[CIN], xC[CIN], xD[CIN];
#pragma unroll
  for (int ci = 0; ci < CIN; ci++) { xA[ci] = xs[ci][0]; xB[ci] = xs[ci][1]; }

  auto step = [&](const float (&A)[CIN], const float (&Bv)[CIN], float (&C)[CIN],
                  int tt, bool warm) {
    const int j = tt + 1 - base;
#pragma unroll
    for (int ci = 0; ci < CIN; ci++) C[ci] = xs[ci][j];
    float a0 = 0.0f, a1 = 0.0f, a2 = 0.0f;  // 3 parallel chains for ILP
#pragma unroll
    for (int ci = 0; ci < CIN; ci++) {
      a0 = fmaf(wa[ci], A[ci], a0);
      a1 = fmaf(wb[ci], Bv[ci], a1);
      a2 = fmaf(wc[ci], C[ci], a2);
    }
    if (warm && tt < 0) return;                    // chunk 0: true start at t=0
    float z = fmaf(((a0 + a1) + a2) + bb, sc, sh); // (conv + b) * scale + shift
    float d = z - v;
    v = fmaf(d, 0.5f, v);                          // v += (x - v)/tau, tau=2
    bool sp = (v >= 1.0f);
    if (!warm) {
      unsigned mk = __ballot_sync(0xffffffffu, sp);
      if ((tt & 31) == lane) keep = mk;            // distribute masks over lanes
      if ((tt & 31) == 31) mrow[tt - 31 + lane] = keep;  // 128B coalesced store
    }
    v = sp ? 0.0f : v;                             // hard reset
  };

  // W = 64 and CH = 512 are multiples of 4: period-4 rotation, no copies.
  for (int t = ts; t < t0; t += 4) {
    step(xA, xB, xC, t, true);  step(xB, xC, xD, t + 1, true);
    step(xC, xD, xA, t + 2, true); step(xD, xA, xB, t + 3, true);
  }
  for (int t = t0; t < te; t += 4) {
    step(xA, xB, xC, t, false); step(xB, xC, xD, t + 1, false);
    step(xC, xD, xA, t + 2, false); step(xD, xA, xB, t + 3, false);
  }
}

// ---------------------------------------------------------------------------
// Kernel B: sparse conv1d(32->64,k=3) + BN + LIF -> out, SCATTER formulation.
// One warp per (batch, chunk); lane covers outputs o=lane and o+32. Each mask
// m(s) is visited ONCE; its bits scatter w[tap2]->acc(s-1), w[tap1]->acc(s),
// w[tap0]->acc(s+1) via three rolling accumulators per output. Per bit: one
// LDS.128 + one LDS.64 (paired weight layout) + 6 FADD, serving 2 outputs x 3
// time taps. After processing m(s), conv(s-1) is complete -> LIF step.
// ---------------------------------------------------------------------------
__global__ __launch_bounds__(32) void lif2_kernel(
    const float* __restrict__ w2,  const float* __restrict__ b2,
    const float* __restrict__ g2,  const float* __restrict__ be2,
    const float* __restrict__ m2,  const float* __restrict__ v2p,
    float* __restrict__ out) {
  __shared__ float w4[H][32][4];   // [c][lane]: {tap2_o, tap1_o, tap0_o, tap2_o2}
  __shared__ float w2x[H][32][2];  // [c][lane]: {tap1_o2, tap0_o2}
  __shared__ unsigned ms[L];
  __shared__ float ot[E][33];      // 32-step spike staging, +1 pad
  const int b    = blockIdx.y;
  const int t0   = blockIdx.x * CH;
  const int ts   = t0 - W;
  const int te   = t0 + CH;
  const int base = ts - 1;
  const int lane = threadIdx.x;
  const int o = lane, o2 = lane + 32;
  const int ws = (ts < 0) ? 0 : ts;  // first LIF-active time

  // Weights: global w2 layout [E][H][3].
  for (int c = 0; c < H; c++) {
    w4[c][lane][0]  = w2[(o  * H + c) * 3 + 2];
    w4[c][lane][1]  = w2[(o  * H + c) * 3 + 1];
    w4[c][lane][2]  = w2[(o  * H + c) * 3 + 0];
    w4[c][lane][3]  = w2[(o2 * H + c) * 3 + 2];
    w2x[c][lane][0] = w2[(o2 * H + c) * 3 + 1];
    w2x[c][lane][1] = w2[(o2 * H + c) * 3 + 0];
  }
  const unsigned* mrow = g_masks + b * T;
  for (int i = lane; i < L; i += 32) {
    int g = base + i;
    ms[i] = (g >= 0 && g < T) ? mrow[g] : 0u;  // zero pad = conv 'same' pad
  }
  const float sc0 = g2[o]  / sqrtf(v2p[o]  + 1e-5f);
  const float sh0 = be2[o]  - m2[o]  * sc0;
  const float bb0 = b2[o];
  const float sc1 = g2[o2] / sqrtf(v2p[o2] + 1e-5f);
  const float sh1 = be2[o2] - m2[o2] * sc1;
  const float bb1 = b2[o2];
  __syncwarp();

  float aP0 = 0.f, aC0 = 0.f, aN0 = 0.f;
  float aP1 = 0.f, aC1 = 0.f, aN1 = 0.f;
  float v0 = 0.f, v1 = 0.f;

  auto step = [&](int s, bool warm) {
    unsigned m = ms[s - base];
    while (m) {                       // block-uniform mask -> no divergence
      int c = __ffs((int)m) - 1;
      m &= m - 1;
      float4 wv = *reinterpret_cast<const float4*>(&w4[c][lane][0]);
      float2 wu = *reinterpret_cast<const float2*>(&w2x[c][lane][0]);
      aP0 += wv.x; aC0 += wv.y; aN0 += wv.z;
      aP1 += wv.w; aC1 += wu.x; aN1 += wu.y;
    }
    const int u = s - 1;              // conv(u) now complete in aP*
    if (!warm || u >= ws) {
      float z0 = fmaf(aP0 + bb0, sc0, sh0);
      float d0 = z0 - v0; v0 = fmaf(d0, 0.5f, v0);
      bool s0 = (v0 >= 1.0f);
      float z1 = fmaf(aP1 + bb1, sc1, sh1);
      float d1 = z1 - v1; v1 = fmaf(d1, 0.5f, v1);
      bool s1 = (v1 >= 1.0f);
      if (!warm) {
        ot[o][u & 31]  = s0 ? 1.0f : 0.0f;   // bank-conflict-free (stride 33)
        ot[o2][u & 31] = s1 ? 1.0f : 0.0f;
      }
      v0 = s0 ? 0.0f : v0;
      v1 = s1 ? 0.0f : v1;
    }
    aP0 = aC0; aC0 = aN0; aN0 = 0.f;   // rotate accumulators
    aP1 = aC1; aC1 = aN1; aN1 = 0.f;
    if (!warm && (u & 31) == 31) {     // flush 64ch x 32t, 128B coalesced rows
      __syncwarp();
      const int tb = u - 31;
#pragma unroll 8
      for (int r = 0; r < E; r++)
        out[(size_t)(b * E + r) * T + tb + lane] = ot[r][lane];
      __syncwarp();
    }
  };

  // Warm-up: s in [ts-1, t0]   (scatter + LIF for u in [ws, t0), no stores)
  for (int s = ts - 1; s <= t0; ++s) step(s, true);
  // Main:    s in [t0+1, te]   (produces u in [t0, te))
#pragma unroll 4
  for (int s = t0 + 1; s <= te; ++s) step(s, false);
}

// ---------------------------------------------------------------------------
extern "C" void kernel_launch(void* const* d_in, const int* in_sizes, int n_in,
                              void* d_out, int out_size) {
  const float* x   = (const float*)d_in[0];
  const float* w1  = (const float*)d_in[1];
  const float* b1  = (const float*)d_in[2];
  const float* g1  = (const float*)d_in[3];
  const float* be1 = (const float*)d_in[4];
  const float* m1  = (const float*)d_in[5];
  const float* v1  = (const float*)d_in[6];
  const float* w2  = (const float*)d_in[7];
  const float* b2  = (const float*)d_in[8];
  const float* g2  = (const float*)d_in[9];
  const float* be2 = (const float*)d_in[10];
  const float* m2  = (const float*)d_in[11];
  const float* v2  = (const float*)d_in[12];
  float* out = (float*)d_out;

  dim3 grid(NC, B);
  lif1_kernel<<<grid, 32>>>(x, w1, b1, g1, be1, m1, v1);
  lif2_kernel<<<grid, 32>>>(w2, b2, g2, be2, m2, v2, out);
}

// round 9
// speedup vs baseline: 1.4732x; 1.4732x over previous
#include <cuda_runtime.h>
#include <math.h>

// Problem constants (fixed by the reference setup_inputs()).
namespace {
constexpr int T   = 16384;
constexpr int B   = 64;
constexpr int CIN = 8;
constexpr int H   = 32;   // hidden channels (layer 1 out)
constexpr int E   = 64;   // embed channels (layer 2 out)
constexpr int CH  = 512;  // time span per block (4 warps x 128)
constexpr int SUB = 128;  // useful steps per warp
constexpr int W   = 64;   // LIF warm-up steps (0.5x decay/step + exact hard resets
                          //  -> sub-chunk state re-converges to true trajectory)
constexpr int NC  = T / CH;     // 32 chunks
constexpr int L   = CH + W + 2; // smem tile span: [t0-W-1, t0+CH]  (578)
}

// Layer-1 spikes as bitmasks: bit c of g_masks[b*T + t] = spike of channel c at t.
__device__ unsigned g_masks[B * T];

typedef unsigned long long ull;

__device__ __forceinline__ ull fma2(ull a, ull b, ull c) {
  ull d; asm("fma.rn.f32x2 %0, %1, %2, %3;" : "=l"(d) : "l"(a), "l"(b), "l"(c));
  return d;
}
__device__ __forceinline__ ull add2(ull a, ull b) {
  ull d; asm("add.rn.f32x2 %0, %1, %2;" : "=l"(d) : "l"(a), "l"(b));
  return d;
}
__device__ __forceinline__ ull pack2(float lo, float hi) {
  ull d; asm("mov.b64 %0, {%1, %2};" : "=l"(d) : "f"(lo), "f"(hi));
  return d;
}
__device__ __forceinline__ void unpack2(ull v, float& lo, float& hi) {
  asm("mov.b64 {%0, %1}, %2;" : "=f"(lo), "=f"(hi) : "l"(v));
}

// ---------------------------------------------------------------------------
// Kernel A: conv1d(8->32,k=3,same) + BN(eval) + LIF  -> spike bitmasks.
// 128-thread block per (batch, 512-chunk); each of 4 warps runs a 128-step
// sub-chunk (+64 warm-up) over a shared x tile. lane = output channel.
// x tile is [t][8ch] so one step = 2x LDS.128; conv = 12x fma.rn.f32x2.
// ---------------------------------------------------------------------------
__global__ __launch_bounds__(128) void lif1_kernel(
    const float* __restrict__ x,  const float* __restrict__ w1,
    const float* __restrict__ b1, const float* __restrict__ g1,
    const float* __restrict__ be1, const float* __restrict__ m1,
    const float* __restrict__ v1) {
  __shared__ __align__(16) float xs[L][CIN];
  const int b    = blockIdx.y;
  const int t0   = blockIdx.x * CH;
  const int base = t0 - W - 1;      // xs[j] = x[b, :, base+j]
  const int tid  = threadIdx.x;
  const int lane = tid & 31;
  const int warp = tid >> 5;

  // Stage x tile (zero-pad outside [0,T) -> also the conv 'same' pads).
  // Read coalesced per channel row; smem store conflicts are negligible.
  for (int i = tid; i < CIN * L; i += 128) {
    int c = i / L, j = i - c * L;
    int g = base + j;
    xs[j][c] = (g >= 0 && g < T) ? x[(b * CIN + c) * T + g] : 0.0f;
  }
  __syncthreads();

  // Per-lane packed weights + BN params (unfused BN mirrors reference algebra).
  const float* wp = w1 + lane * (CIN * 3);
  ull wa[4], wb[4], wc[4];
#pragma unroll
  for (int p = 0; p < 4; p++) {
    wa[p] = pack2(wp[(2 * p) * 3 + 0], wp[(2 * p + 1) * 3 + 0]);
    wb[p] = pack2(wp[(2 * p) * 3 + 1], wp[(2 * p + 1) * 3 + 1]);
    wc[p] = pack2(wp[(2 * p) * 3 + 2], wp[(2 * p + 1) * 3 + 2]);
  }
  const float sc = g1[lane] / sqrtf(v1[lane] + 1e-5f);
  const float sh = be1[lane] - m1[lane] * sc;
  const float bb = b1[lane];

  const int start = t0 + warp * SUB;  // this warp's sub-chunk
  const int sw    = start - W;        // warm-up start (negative only for chunk 0)
  float v = 0.0f;
  unsigned keep = 0;
  unsigned* mrow = g_masks + b * T;

  // Rotating packed x windows: A=x(t-1), B=x(t), C<-x(t+1); period-4 rotation.
  ull A[4], Bv[4], C[4], D[4];
  {
    int j = sw - 1 - base;  // = warp*SUB
    const ulonglong2* r = reinterpret_cast<const ulonglong2*>(xs[j]);
    ulonglong2 q0 = r[0], q1 = r[1];
    A[0] = q0.x; A[1] = q0.y; A[2] = q1.x; A[3] = q1.y;
    r  = reinterpret_cast<const ulonglong2*>(xs[j + 1]);
    q0 = r[0]; q1 = r[1];
    Bv[0] = q0.x; Bv[1] = q0.y; Bv[2] = q1.x; Bv[3] = q1.y;
  }

  auto conv = [&](const ull (&P)[4], const ull (&Q)[4], ull (&R)[4],
                  int tt) -> float {
    const int j = tt + 1 - base;
    const ulonglong2* r = reinterpret_cast<const ulonglong2*>(xs[j]);
    ulonglong2 q0 = r[0], q1 = r[1];
    R[0] = q0.x; R[1] = q0.y; R[2] = q1.x; R[3] = q1.y;
    ull a0 = 0, a1 = 0, a2 = 0;   // 0 bits == packed {0.f, 0.f}
#pragma unroll
    for (int p = 0; p < 4; p++) {
      a0 = fma2(wa[p], P[p], a0);
      a1 = fma2(wb[p], Q[p], a1);
      a2 = fma2(wc[p], R[p], a2);
    }
    float lo, hi;
    unpack2(add2(add2(a0, a1), a2), lo, hi);
    return lo + hi;
  };

  auto wstep = [&](const ull (&P)[4], const ull (&Q)[4], ull (&R)[4], int tt) {
    float cv = conv(P, Q, R, tt);
    if (tt >= 0) {                              // chunk 0: true start at t=0
      float z = fmaf(cv + bb, sc, sh);          // (conv + b)*scale + shift
      v = fmaf(z - v, 0.5f, v);                 // v += (x - v)/tau, tau=2
      if (v >= 1.0f) v = 0.0f;                  // hard reset
    }
  };
  auto mstep = [&](const ull (&P)[4], const ull (&Q)[4], ull (&R)[4], int tt) {
    float cv = conv(P, Q, R, tt);
    float z = fmaf(cv + bb, sc, sh);
    v = fmaf(z - v, 0.5f, v);
    bool sp = (v >= 1.0f);
    unsigned mk = __ballot_sync(0xffffffffu, sp);
    if (sp) v = 0.0f;
    if ((tt & 31) == lane) keep = mk;           // distribute masks over lanes
    if ((tt & 31) == 31) mrow[tt - 31 + lane] = keep;  // 128B coalesced store
  };

  // W and SUB are multiples of 4: period-4 rotation, no copies.
  for (int t = sw; t < start; t += 4) {
    wstep(A, Bv, C, t);   wstep(Bv, C, D, t + 1);
    wstep(C, D, A, t + 2); wstep(D, A, Bv, t + 3);
  }
  for (int t = start; t < start + SUB; t += 4) {
    mstep(A, Bv, C, t);   mstep(Bv, C, D, t + 1);
    mstep(C, D, A, t + 2); mstep(D, A, Bv, t + 3);
  }
}

// ---------------------------------------------------------------------------
// Kernel B: sparse conv1d(32->64,k=3) + BN + LIF -> out, SCATTER formulation.
// 128-thread block per (batch, 512-chunk); each of 4 warps runs a 128-step
// sub-chunk (+64 warm-up), sharing the 24KB weight table + mask tile. Lane
// covers outputs o=lane, o+32. Each mask m(s) is visited ONCE; its bits
// scatter taps into 3 rolling accumulators per output (1 LDS.128 + 1 LDS.64 +
// 6 FADD per bit, serving 2 outputs x 3 taps). After m(s), conv(s-1) is done.
// ---------------------------------------------------------------------------
__global__ __launch_bounds__(128) void lif2_kernel(
    const float* __restrict__ w2,  const float* __restrict__ b2,
    const float* __restrict__ g2,  const float* __restrict__ be2,
    const float* __restrict__ m2,  const float* __restrict__ v2p,
    float* __restrict__ out) {
  __shared__ float w4[H][32][4];   // [c][lane]: {tap2_o, tap1_o, tap0_o, tap2_o2}
  __shared__ float w2x[H][32][2];  // [c][lane]: {tap1_o2, tap0_o2}
  __shared__ unsigned ms[L];
  __shared__ float ot[4][E][17];   // per-warp 16-step spike staging (+1 pad)
  const int b    = blockIdx.y;
  const int t0   = blockIdx.x * CH;
  const int base = t0 - W - 1;
  const int tid  = threadIdx.x;
  const int lane = tid & 31;
  const int warp = tid >> 5;

  // Weights: global w2 layout [E][H][3] -> paired smem layout.
  for (int i = tid; i < H * 32; i += 128) {
    int c = i >> 5, ln = i & 31;
    int o = ln, o2 = ln + 32;
    w4[c][ln][0]  = w2[(o  * H + c) * 3 + 2];
    w4[c][ln][1]  = w2[(o  * H + c) * 3 + 1];
    w4[c][ln][2]  = w2[(o  * H + c) * 3 + 0];
    w4[c][ln][3]  = w2[(o2 * H + c) * 3 + 2];
    w2x[c][ln][0] = w2[(o2 * H + c) * 3 + 1];
    w2x[c][ln][1] = w2[(o2 * H + c) * 3 + 0];
  }
  const unsigned* mrow = g_masks + b * T;
  for (int i = tid; i < L; i += 128) {
    int g = base + i;
    ms[i] = (g >= 0 && g < T) ? mrow[g] : 0u;  // zero pad = conv 'same' pad
  }
  const int o = lane, o2 = lane + 32;
  const float sc0 = g2[o]  / sqrtf(v2p[o]  + 1e-5f);
  const float sh0 = be2[o]  - m2[o]  * sc0;
  const float bb0 = b2[o];
  const float sc1 = g2[o2] / sqrtf(v2p[o2] + 1e-5f);
  const float sh1 = be2[o2] - m2[o2] * sc1;
  const float bb1 = b2[o2];
  __syncthreads();

  const int start = t0 + warp * SUB;
  const int end   = start + SUB;
  const int sw    = start - W;
  const int ws    = (sw < 0) ? 0 : sw;   // first LIF-active time

  float aP0 = 0.f, aC0 = 0.f, aN0 = 0.f;
  float aP1 = 0.f, aC1 = 0.f, aN1 = 0.f;
  float v0 = 0.f, v1 = 0.f;

  auto scatter = [&](int s) {
    unsigned m = ms[s - base];
    while (m) {                          // warp-uniform mask -> no divergence
      int c = __ffs((int)m) - 1;
      m &= m - 1;
      float4 wv = *reinterpret_cast<const float4*>(&w4[c][lane][0]);
      float2 wu = *reinterpret_cast<const float2*>(&w2x[c][lane][0]);
      aP0 += wv.x; aC0 += wv.y; aN0 += wv.z;
      aP1 += wv.w; aC1 += wu.x; aN1 += wu.y;
    }
  };
  auto rot = [&] {
    aP0 = aC0; aC0 = aN0; aN0 = 0.f;
    aP1 = aC1; aC1 = aN1; aN1 = 0.f;
  };

  // Phase 1: scatter only (u = s-1 < ws; no LIF yet).
  for (int s = sw - 1; s <= ws; ++s) { scatter(s); rot(); }
  // Phase 2: warm LIF, no stores (u in [ws, start)).
  for (int s = ws + 1; s <= start; ++s) {
    scatter(s);
    float z0 = fmaf(aP0 + bb0, sc0, sh0);
    v0 = fmaf(z0 - v0, 0.5f, v0);
    if (v0 >= 1.0f) v0 = 0.0f;
    float z1 = fmaf(aP1 + bb1, sc1, sh1);
    v1 = fmaf(z1 - v1, 0.5f, v1);
    if (v1 >= 1.0f) v1 = 0.0f;
    rot();
  }
  // Phase 3: LIF + stores (u in [start, end)), flush every 16 steps.
  for (int s = start + 1; s <= end; ++s) {
    scatter(s);
    const int u = s - 1;
    float z0 = fmaf(aP0 + bb0, sc0, sh0);
    v0 = fmaf(z0 - v0, 0.5f, v0);
    bool s0 = (v0 >= 1.0f);
    float z1 = fmaf(aP1 + bb1, sc1, sh1);
    v1 = fmaf(z1 - v1, 0.5f, v1);
    bool s1 = (v1 >= 1.0f);
    ot[warp][o][u & 15]  = s0 ? 1.0f : 0.0f;   // stride-17: conflict-free
    ot[warp][o2][u & 15] = s1 ? 1.0f : 0.0f;
    v0 = s0 ? 0.0f : v0;
    v1 = s1 ? 0.0f : v1;
    rot();
    if ((u & 15) == 15) {                      // warp-uniform flush
      __syncwarp();
      const int rp = lane >> 4, col = lane & 15;
      const int tb = u - 15;
#pragma unroll 8
      for (int r = rp; r < E; r += 2)          // 64B contiguous per half-warp
        out[(size_t)(b * E + r) * T + tb + col] = ot[warp][r][col];
      __syncwarp();
    }
  }
}

// ---------------------------------------------------------------------------
extern "C" void kernel_launch(void* const* d_in, const int* in_sizes, int n_in,
                              void* d_out, int out_size) {
  const float* x   = (const float*)d_in[0];
  const float* w1  = (const float*)d_in[1];
  const float* b1  = (const float*)d_in[2];
  const float* g1  = (const float*)d_in[3];
  const float* be1 = (const float*)d_in[4];
  const float* m1  = (const float*)d_in[5];
  const float* v1  = (const float*)d_in[6];
  const float* w2  = (const float*)d_in[7];
  const float* b2  = (const float*)d_in[8];
  const float* g2  = (const float*)d_in[9];
  const float* be2 = (const float*)d_in[10];
  const float* m2  = (const float*)d_in[11];
  const float* v2  = (const float*)d_in[12];
  float* out = (float*)d_out;

  dim3 grid(NC, B);
  lif1_kernel<<<grid, 128>>>(x, w1, b1, g1, be1, m1, v1);
  lif2_kernel<<<grid, 128>>>(w2, b2, g2, be2, m2, v2, out);
}

// round 11
// speedup vs baseline: 1.6217x; 1.1008x over previous
#include <cuda_runtime.h>
#include <math.h>

// Problem constants (fixed by the reference setup_inputs()).
namespace {
constexpr int T   = 16384;
constexpr int B   = 64;
constexpr int CIN = 8;
constexpr int H   = 32;   // hidden channels (layer 1 out)
constexpr int E   = 64;   // embed channels (layer 2 out)
constexpr int CH  = 512;  // time span per block (4 warps x 128)
constexpr int SUB = 128;  // useful steps per warp
constexpr int W   = 32;   // LIF warm-up steps: state error <= 2^-32 (0.5x decay
                          //  per step) and exact after any coincident hard reset
constexpr int NC  = T / CH;     // 32 chunks
constexpr int L   = CH + W + 2; // smem tile span: [t0-W-1, t0+CH]  (546)
}

// Layer-1 spikes as bitmasks: bit c of g_masks[b*T + t] = spike of channel c at t.
__device__ unsigned g_masks[B * T];

typedef unsigned long long ull;

__device__ __forceinline__ ull fma2(ull a, ull b, ull c) {
  ull d; asm("fma.rn.f32x2 %0, %1, %2, %3;" : "=l"(d) : "l"(a), "l"(b), "l"(c));
  return d;
}
__device__ __forceinline__ ull add2(ull a, ull b) {
  ull d; asm("add.rn.f32x2 %0, %1, %2;" : "=l"(d) : "l"(a), "l"(b));
  return d;
}
__device__ __forceinline__ ull pack2(float lo, float hi) {
  ull d; asm("mov.b64 %0, {%1, %2};" : "=l"(d) : "f"(lo), "f"(hi));
  return d;
}
__device__ __forceinline__ void unpack2(ull v, float& lo, float& hi) {
  asm("mov.b64 {%0, %1}, %2;" : "=f"(lo), "=f"(hi) : "l"(v));
}

// ---------------------------------------------------------------------------
// Kernel A: conv1d(8->32,k=3,same) + BN(eval) + LIF  -> spike bitmasks.
// 128-thread block per (batch, 512-chunk); each of 4 warps runs a 128-step
// sub-chunk (+32 warm-up) over a shared x tile. lane = output channel.
// x tile is [t][8ch] so one step = 2x LDS.128 broadcast; conv = 12x fma.f32x2.
// ---------------------------------------------------------------------------
__global__ __launch_bounds__(128, 6) void lif1_kernel(
    const float* __restrict__ x,  const float* __restrict__ w1,
    const float* __restrict__ b1, const float* __restrict__ g1,
    const float* __restrict__ be1, const float* __restrict__ m1,
    const float* __restrict__ v1) {
  __shared__ __align__(16) float xs[L][CIN];
  const int b    = blockIdx.y;
  const int t0   = blockIdx.x * CH;
  const int base = t0 - W - 1;      // xs[j] = x[b, :, base+j]
  const int tid  = threadIdx.x;
  const int lane = tid & 31;
  const int warp = tid >> 5;

  // Stage x tile (zero-pad outside [0,T) -> also the conv 'same' pads).
  for (int i = tid; i < CIN * L; i += 128) {
    int c = i / L, j = i - c * L;
    int g = base + j;
    xs[j][c] = (g >= 0 && g < T) ? x[(b * CIN + c) * T + g] : 0.0f;
  }
  __syncthreads();

  // Per-lane packed weights + BN params (unfused BN mirrors reference algebra).
  const float* wp = w1 + lane * (CIN * 3);
  ull wa[4], wb[4], wc[4];
#pragma unroll
  for (int p = 0; p < 4; p++) {
    wa[p] = pack2(wp[(2 * p) * 3 + 0], wp[(2 * p + 1) * 3 + 0]);
    wb[p] = pack2(wp[(2 * p) * 3 + 1], wp[(2 * p + 1) * 3 + 1]);
    wc[p] = pack2(wp[(2 * p) * 3 + 2], wp[(2 * p + 1) * 3 + 2]);
  }
  const float sc = g1[lane] / sqrtf(v1[lane] + 1e-5f);
  const float sh = be1[lane] - m1[lane] * sc;
  const float bb = b1[lane];

  const int start = t0 + warp * SUB;  // this warp's sub-chunk
  const int sw    = start - W;        // warm-up start (negative only for chunk 0)
  float v = 0.0f;
  unsigned keep = 0;
  unsigned* mrow = g_masks + b * T;

  // Rotating packed x windows: A=x(t-1), B=x(t), C<-x(t+1); period-4 rotation.
  ull A[4], Bv[4], C[4], D[4];
  {
    int j = sw - 1 - base;  // = warp*SUB
    const ulonglong2* r = reinterpret_cast<const ulonglong2*>(xs[j]);
    ulonglong2 q0 = r[0], q1 = r[1];
    A[0] = q0.x; A[1] = q0.y; A[2] = q1.x; A[3] = q1.y;
    r  = reinterpret_cast<const ulonglong2*>(xs[j + 1]);
    q0 = r[0]; q1 = r[1];
    Bv[0] = q0.x; Bv[1] = q0.y; Bv[2] = q1.x; Bv[3] = q1.y;
  }

  auto conv = [&](const ull (&P)[4], const ull (&Q)[4], ull (&R)[4],
                  int tt) -> float {
    const int j = tt + 1 - base;
    const ulonglong2* r = reinterpret_cast<const ulonglong2*>(xs[j]);
    ulonglong2 q0 = r[0], q1 = r[1];
    R[0] = q0.x; R[1] = q0.y; R[2] = q1.x; R[3] = q1.y;
    ull a0 = 0, a1 = 0, a2 = 0;   // 0 bits == packed {0.f, 0.f}
#pragma unroll
    for (int p = 0; p < 4; p++) {
      a0 = fma2(wa[p], P[p], a0);
      a1 = fma2(wb[p], Q[p], a1);
      a2 = fma2(wc[p], R[p], a2);
    }
    float lo, hi;
    unpack2(add2(add2(a0, a1), a2), lo, hi);
    return lo + hi;
  };

  auto wstep = [&](const ull (&P)[4], const ull (&Q)[4], ull (&R)[4], int tt) {
    float cv = conv(P, Q, R, tt);
    if (tt >= 0) {                              // chunk 0: true start at t=0
      float z = fmaf(cv + bb, sc, sh);          // (conv + b)*scale + shift
      v = fmaf(z - v, 0.5f, v);                 // v += (x - v)/tau, tau=2
      if (v >= 1.0f) v = 0.0f;                  // hard reset
    }
  };
  auto mstep = [&](const ull (&P)[4], const ull (&Q)[4], ull (&R)[4], int tt) {
    float cv = conv(P, Q, R, tt);
    float z = fmaf(cv + bb, sc, sh);
    v = fmaf(z - v, 0.5f, v);
    bool sp = (v >= 1.0f);
    unsigned mk = __ballot_sync(0xffffffffu, sp);
    if (sp) v = 0.0f;
    if ((tt & 31) == lane) keep = mk;           // distribute masks over lanes
    if ((tt & 31) == 31) mrow[tt - 31 + lane] = keep;  // 128B coalesced store
  };

  // W and SUB are multiples of 4: period-4 rotation, no copies.
  for (int t = sw; t < start; t += 4) {
    wstep(A, Bv, C, t);   wstep(Bv, C, D, t + 1);
    wstep(C, D, A, t + 2); wstep(D, A, Bv, t + 3);
  }
  for (int t = start; t < start + SUB; t += 4) {
    mstep(A, Bv, C, t);   mstep(Bv, C, D, t + 1);
    mstep(C, D, A, t + 2); mstep(D, A, Bv, t + 3);
  }
}

// ---------------------------------------------------------------------------
// Kernel B: sparse conv1d(32->64,k=3) + BN + LIF -> out, SCATTER formulation.
// 128-thread block per (batch, 512-chunk); 4 warps x 128-step sub-chunks
// (+32 warm-up) sharing the weight tables + mask tile. Lane covers outputs
// o=lane, o+32 via PAIR-PACKED weights: per bit one LDS.128 {tap2(o,o2),
// tap1(o,o2)} + one LDS.64 {tap0(o,o2)} + 3x add.rn.f32x2 into packed rolling
// accumulators. After m(s), conv(s-1) is complete in aP -> LIF step.
// ---------------------------------------------------------------------------
__global__ __launch_bounds__(128, 6) void lif2_kernel(
    const float* __restrict__ w2,  const float* __restrict__ b2,
    const float* __restrict__ g2,  const float* __restrict__ be2,
    const float* __restrict__ m2,  const float* __restrict__ v2p,
    float* __restrict__ out) {
  __shared__ __align__(16) float w4[H][32][4];  // [c][ln]: {t2_o,t2_o2,t1_o,t1_o2}
  __shared__ __align__(8)  float w2x[H][32][2]; // [c][ln]: {t0_o,t0_o2}
  __shared__ unsigned ms[L];
  __shared__ float ot[4][E][9];    // per-warp 8-step spike staging (+1 pad)
  const int b    = blockIdx.y;
  const int t0   = blockIdx.x * CH;
  const int base = t0 - W - 1;
  const int tid  = threadIdx.x;
  const int lane = tid & 31;
  const int warp = tid >> 5;

  // Weights: global w2 layout [E][H][3] -> pair-packed smem layout.
  for (int i = tid; i < H * 32; i += 128) {
    int c = i >> 5, ln = i & 31;
    int o = ln, o2 = ln + 32;
    w4[c][ln][0]  = w2[(o  * H + c) * 3 + 2];
    w4[c][ln][1]  = w2[(o2 * H + c) * 3 + 2];
    w4[c][ln][2]  = w2[(o  * H + c) * 3 + 1];
    w4[c][ln][3]  = w2[(o2 * H + c) * 3 + 1];
    w2x[c][ln][0] = w2[(o  * H + c) * 3 + 0];
    w2x[c][ln][1] = w2[(o2 * H + c) * 3 + 0];
  }
  const unsigned* mrow = g_masks + b * T;
  for (int i = tid; i < L; i += 128) {
    int g = base + i;
    ms[i] = (g >= 0 && g < T) ? mrow[g] : 0u;  // zero pad = conv 'same' pad
  }
  const int o = lane, o2 = lane + 32;
  const float sc0 = g2[o]  / sqrtf(v2p[o]  + 1e-5f);
  const float sh0 = be2[o]  - m2[o]  * sc0;
  const float bb0 = b2[o];
  const float sc1 = g2[o2] / sqrtf(v2p[o2] + 1e-5f);
  const float sh1 = be2[o2] - m2[o2] * sc1;
  const float bb1 = b2[o2];
  __syncthreads();

  const int start = t0 + warp * SUB;
  const int end   = start + SUB;
  const int sw    = start - W;
  const int ws    = (sw < 0) ? 0 : sw;   // first LIF-active time

  ull aP = 0, aC = 0, aN = 0;            // packed (o, o2) rolling accumulators
  float v0 = 0.f, v1 = 0.f;

  auto scatter = [&](int s) {
    unsigned m = ms[s - base];
    while (m) {                          // warp-uniform mask -> no divergence
      int c = __ffs((int)m) - 1;
      m &= m - 1;
      ulonglong2 wv = *reinterpret_cast<const ulonglong2*>(&w4[c][lane][0]);
      aP = add2(aP, wv.x);               // tap2 pair -> conv(s-1)
      aC = add2(aC, wv.y);               // tap1 pair -> conv(s)
      aN = add2(aN, *reinterpret_cast<const ull*>(&w2x[c][lane][0]));
    }
  };
  auto rot = [&] { aP = aC; aC = aN; aN = 0; };

  // Phase 1: scatter only (u = s-1 < ws; no LIF yet).
  for (int s = sw - 1; s <= ws; ++s) { scatter(s); rot(); }
  // Phase 2: warm LIF, no stores (u in [ws, start)).
  for (int s = ws + 1; s <= start; ++s) {
    scatter(s);
    float p0, p1; unpack2(aP, p0, p1);
    float z0 = fmaf(p0 + bb0, sc0, sh0);
    v0 = fmaf(z0 - v0, 0.5f, v0);
    if (v0 >= 1.0f) v0 = 0.0f;
    float z1 = fmaf(p1 + bb1, sc1, sh1);
    v1 = fmaf(z1 - v1, 0.5f, v1);
    if (v1 >= 1.0f) v1 = 0.0f;
    rot();
  }
  // Phase 3: LIF + stores (u in [start, end)), flush every 8 steps.
  for (int s = start + 1; s <= end; ++s) {
    scatter(s);
    const int u = s - 1;
    float p0, p1; unpack2(aP, p0, p1);
    float z0 = fmaf(p0 + bb0, sc0, sh0);
    v0 = fmaf(z0 - v0, 0.5f, v0);
    bool s0 = (v0 >= 1.0f);
    float z1 = fmaf(p1 + bb1, sc1, sh1);
    v1 = fmaf(z1 - v1, 0.5f, v1);
    bool s1 = (v1 >= 1.0f);
    ot[warp][o][u & 7]  = s0 ? 1.0f : 0.0f;    // stride-9: conflict-free
    ot[warp][o2][u & 7] = s1 ? 1.0f : 0.0f;
    v0 = s0 ? 0.0f : v0;
    v1 = s1 ? 0.0f : v1;
    rot();
    if ((u & 7) == 7) {                        // warp-uniform flush
      __syncwarp();
      const int col = lane & 7;
      const int tb = u - 7;
#pragma unroll 4
      for (int r = lane >> 3; r < E; r += 4)   // 32B sectors, fully utilized
        out[(size_t)(b * E + r) * T + tb + col] = ot[warp][r][col];
      __syncwarp();
    }
  }
}

// ---------------------------------------------------------------------------
extern "C" void kernel_launch(void* const* d_in, const int* in_sizes, int n_in,
                              void* d_out, int out_size) {
  const float* x   = (const float*)d_in[0];
  const float* w1  = (const float*)d_in[1];
  const float* b1  = (const float*)d_in[2];
  const float* g1  = (const float*)d_in[3];
  const float* be1 = (const float*)d_in[4];
  const float* m1  = (const float*)d_in[5];
  const float* v1  = (const float*)d_in[6];
  const float* w2  = (const float*)d_in[7];
  const float* b2  = (const float*)d_in[8];
  const float* g2  = (const float*)d_in[9];
  const float* be2 = (const float*)d_in[10];
  const float* m2  = (const float*)d_in[11];
  const float* v2  = (const float*)d_in[12];
  float* out = (float*)d_out;

  dim3 grid(NC, B);
  lif1_kernel<<<grid, 128>>>(x, w1, b1, g1, be1, m1, v1);
  lif2_kernel<<<grid, 128>>>(w2, b2, g2, be2, m2, v2, out);
}

// round 12
// speedup vs baseline: 1.9201x; 1.1840x over previous
#include <cuda_runtime.h>
#include <math.h>

// Problem constants (fixed by the reference setup_inputs()).
namespace {
constexpr int T   = 16384;
constexpr int B   = 64;
constexpr int CIN = 8;
constexpr int H   = 32;   // hidden channels (layer 1 out)
constexpr int E   = 64;   // embed channels (layer 2 out)
constexpr int W   = 32;   // LIF warm-up steps: state error <= 2^-32 (0.5x decay
                          //  per step) and exact after any coincident hard reset
constexpr int SUB = 128;  // useful steps per warp (both kernels)

// Kernel A tiling: 4 warps x 128 steps.
constexpr int CH1 = 512;
constexpr int NC1 = T / CH1;       // 32 chunks
constexpr int L1  = CH1 + W + 2;   // 546

// Kernel B tiling: 8 warps x 128 steps (weight tables amortized over 8 warps).
constexpr int CH2 = 1024;
constexpr int NC2 = T / CH2;       // 16 chunks
constexpr int L2  = CH2 + W + 2;   // 1058
}

// Layer-1 spikes as bitmasks: bit c of g_masks[b*T + t] = spike of channel c at t.
__device__ unsigned g_masks[B * T];

typedef unsigned long long ull;

__device__ __forceinline__ ull fma2(ull a, ull b, ull c) {
  ull d; asm("fma.rn.f32x2 %0, %1, %2, %3;" : "=l"(d) : "l"(a), "l"(b), "l"(c));
  return d;
}
__device__ __forceinline__ ull add2(ull a, ull b) {
  ull d; asm("add.rn.f32x2 %0, %1, %2;" : "=l"(d) : "l"(a), "l"(b));
  return d;
}
__device__ __forceinline__ ull pack2(float lo, float hi) {
  ull d; asm("mov.b64 %0, {%1, %2};" : "=l"(d) : "f"(lo), "f"(hi));
  return d;
}
__device__ __forceinline__ void unpack2(ull v, float& lo, float& hi) {
  asm("mov.b64 {%0, %1}, %2;" : "=f"(lo), "=f"(hi) : "l"(v));
}

// ---------------------------------------------------------------------------
// Kernel A: conv1d(8->32,k=3,same) + BN(eval) + LIF  -> spike bitmasks.
// 128-thread block per (batch, 512-chunk); each of 4 warps runs a 128-step
// sub-chunk (+32 warm-up) over a shared x tile. lane = output channel.
// x tile is [t][8ch] so one step = 2x LDS.128 broadcast; conv = 12x fma.f32x2.
// ---------------------------------------------------------------------------
__global__ __launch_bounds__(128, 6) void lif1_kernel(
    const float* __restrict__ x,  const float* __restrict__ w1,
    const float* __restrict__ b1, const float* __restrict__ g1,
    const float* __restrict__ be1, const float* __restrict__ m1,
    const float* __restrict__ v1) {
  __shared__ __align__(16) float xs[L1][CIN];
  const int b    = blockIdx.y;
  const int t0   = blockIdx.x * CH1;
  const int base = t0 - W - 1;      // xs[j] = x[b, :, base+j]
  const int tid  = threadIdx.x;
  const int lane = tid & 31;
  const int warp = tid >> 5;

  // Stage x tile (zero-pad outside [0,T) -> also the conv 'same' pads).
  for (int i = tid; i < CIN * L1; i += 128) {
    int c = i / L1, j = i - c * L1;
    int g = base + j;
    xs[j][c] = (g >= 0 && g < T) ? x[(b * CIN + c) * T + g] : 0.0f;
  }
  __syncthreads();

  // Per-lane packed weights + BN params (unfused BN mirrors reference algebra).
  const float* wp = w1 + lane * (CIN * 3);
  ull wa[4], wb[4], wc[4];
#pragma unroll
  for (int p = 0; p < 4; p++) {
    wa[p] = pack2(wp[(2 * p) * 3 + 0], wp[(2 * p + 1) * 3 + 0]);
    wb[p] = pack2(wp[(2 * p) * 3 + 1], wp[(2 * p + 1) * 3 + 1]);
    wc[p] = pack2(wp[(2 * p) * 3 + 2], wp[(2 * p + 1) * 3 + 2]);
  }
  const float sc = g1[lane] / sqrtf(v1[lane] + 1e-5f);
  const float sh = be1[lane] - m1[lane] * sc;
  const float bb = b1[lane];

  const int start = t0 + warp * SUB;  // this warp's sub-chunk
  const int sw    = start - W;        // warm-up start (negative only for chunk 0)
  float v = 0.0f;
  unsigned keep = 0;
  unsigned* mrow = g_masks + b * T;

  // Rotating packed x windows: A=x(t-1), B=x(t), C<-x(t+1); period-4 rotation.
  ull A[4], Bv[4], C[4], D[4];
  {
    int j = sw - 1 - base;  // = warp*SUB
    const ulonglong2* r = reinterpret_cast<const ulonglong2*>(xs[j]);
    ulonglong2 q0 = r[0], q1 = r[1];
    A[0] = q0.x; A[1] = q0.y; A[2] = q1.x; A[3] = q1.y;
    r  = reinterpret_cast<const ulonglong2*>(xs[j + 1]);
    q0 = r[0]; q1 = r[1];
    Bv[0] = q0.x; Bv[1] = q0.y; Bv[2] = q1.x; Bv[3] = q1.y;
  }

  auto conv = [&](const ull (&P)[4], const ull (&Q)[4], ull (&R)[4],
                  int tt) -> float {
    const int j = tt + 1 - base;
    const ulonglong2* r = reinterpret_cast<const ulonglong2*>(xs[j]);
    ulonglong2 q0 = r[0], q1 = r[1];
    R[0] = q0.x; R[1] = q0.y; R[2] = q1.x; R[3] = q1.y;
    ull a0 = 0, a1 = 0, a2 = 0;   // 0 bits == packed {0.f, 0.f}
#pragma unroll
    for (int p = 0; p < 4; p++) {
      a0 = fma2(wa[p], P[p], a0);
      a1 = fma2(wb[p], Q[p], a1);
      a2 = fma2(wc[p], R[p], a2);
    }
    float lo, hi;
    unpack2(add2(add2(a0, a1), a2), lo, hi);
    return lo + hi;
  };

  auto wstep = [&](const ull (&P)[4], const ull (&Q)[4], ull (&R)[4], int tt) {
    float cv = conv(P, Q, R, tt);
    if (tt >= 0) {                              // chunk 0: true start at t=0
      float z = fmaf(cv + bb, sc, sh);          // (conv + b)*scale + shift
      v = fmaf(z - v, 0.5f, v);                 // v += (x - v)/tau, tau=2
      if (v >= 1.0f) v = 0.0f;                  // hard reset
    }
  };
  auto mstep = [&](const ull (&P)[4], const ull (&Q)[4], ull (&R)[4], int tt) {
    float cv = conv(P, Q, R, tt);
    float z = fmaf(cv + bb, sc, sh);
    v = fmaf(z - v, 0.5f, v);
    bool sp = (v >= 1.0f);
    unsigned mk = __ballot_sync(0xffffffffu, sp);
    if (sp) v = 0.0f;
    if ((tt & 31) == lane) keep = mk;           // distribute masks over lanes
    if ((tt & 31) == 31) mrow[tt - 31 + lane] = keep;  // 128B coalesced store
  };

  // W and SUB are multiples of 4: period-4 rotation, no copies.
  for (int t = sw; t < start; t += 4) {
    wstep(A, Bv, C, t);   wstep(Bv, C, D, t + 1);
    wstep(C, D, A, t + 2); wstep(D, A, Bv, t + 3);
  }
  for (int t = start; t < start + SUB; t += 4) {
    mstep(A, Bv, C, t);   mstep(Bv, C, D, t + 1);
    mstep(C, D, A, t + 2); mstep(D, A, Bv, t + 3);
  }
}

// ---------------------------------------------------------------------------
// Kernel B: sparse conv1d(32->64,k=3) + BN + LIF -> out, SCATTER formulation.
// 256-thread block per (batch, 1024-chunk); 8 warps x 128-step sub-chunks
// (+32 warm-up) share ONE weight table + mask tile (amortized 2x better than
// the 4-warp version). Lane covers outputs o=lane, o+32 via PAIR-PACKED
// weights: per bit one LDS.128 {tap2(o,o2), tap1(o,o2)} + one LDS.64
// {tap0(o,o2)} + 3x add.rn.f32x2 into packed rolling accumulators.
// After m(s), conv(s-1) is complete in aP -> LIF step.
// ---------------------------------------------------------------------------
__global__ __launch_bounds__(256, 4) void lif2_kernel(
    const float* __restrict__ w2,  const float* __restrict__ b2,
    const float* __restrict__ g2,  const float* __restrict__ be2,
    const float* __restrict__ m2,  const float* __restrict__ v2p,
    float* __restrict__ out) {
  __shared__ __align__(16) float w4[H][32][4];  // [c][ln]: {t2_o,t2_o2,t1_o,t1_o2}
  __shared__ __align__(8)  float w2x[H][32][2]; // [c][ln]: {t0_o,t0_o2}
  __shared__ unsigned ms[L2];
  __shared__ float ot[8][E][9];    // per-warp 8-step spike staging (+1 pad)
  const int b    = blockIdx.y;
  const int t0   = blockIdx.x * CH2;
  const int base = t0 - W - 1;
  const int tid  = threadIdx.x;
  const int lane = tid & 31;
  const int warp = tid >> 5;

  // Weights: global w2 layout [E][H][3] -> pair-packed smem layout.
  for (int i = tid; i < H * 32; i += 256) {
    int c = i >> 5, ln = i & 31;
    int o = ln, o2 = ln + 32;
    w4[c][ln][0]  = w2[(o  * H + c) * 3 + 2];
    w4[c][ln][1]  = w2[(o2 * H + c) * 3 + 2];
    w4[c][ln][2]  = w2[(o  * H + c) * 3 + 1];
    w4[c][ln][3]  = w2[(o2 * H + c) * 3 + 1];
    w2x[c][ln][0] = w2[(o  * H + c) * 3 + 0];
    w2x[c][ln][1] = w2[(o2 * H + c) * 3 + 0];
  }
  const unsigned* mrow = g_masks + b * T;
  for (int i = tid; i < L2; i += 256) {
    int g = base + i;
    ms[i] = (g >= 0 && g < T) ? mrow[g] : 0u;  // zero pad = conv 'same' pad
  }
  const int o = lane, o2 = lane + 32;
  const float sc0 = g2[o]  / sqrtf(v2p[o]  + 1e-5f);
  const float sh0 = be2[o]  - m2[o]  * sc0;
  const float bb0 = b2[o];
  const float sc1 = g2[o2] / sqrtf(v2p[o2] + 1e-5f);
  const float sh1 = be2[o2] - m2[o2] * sc1;
  const float bb1 = b2[o2];
  __syncthreads();

  const int start = t0 + warp * SUB;
  const int end   = start + SUB;
  const int sw    = start - W;
  const int ws    = (sw < 0) ? 0 : sw;   // first LIF-active time

  ull aP = 0, aC = 0, aN = 0;            // packed (o, o2) rolling accumulators
  float v0 = 0.f, v1 = 0.f;

  auto scatter = [&](int s) {
    unsigned m = ms[s - base];
    while (m) {                          // warp-uniform mask -> no divergence
      int c = __ffs((int)m) - 1;
      m &= m - 1;
      ulonglong2 wv = *reinterpret_cast<const ulonglong2*>(&w4[c][lane][0]);
      aP = add2(aP, wv.x);               // tap2 pair -> conv(s-1)
      aC = add2(aC, wv.y);               // tap1 pair -> conv(s)
      aN = add2(aN, *reinterpret_cast<const ull*>(&w2x[c][lane][0]));
    }
  };
  auto rot = [&] { aP = aC; aC = aN; aN = 0; };

  // Phase 1: scatter only (u = s-1 < ws; no LIF yet).
  for (int s = sw - 1; s <= ws; ++s) { scatter(s); rot(); }
  // Phase 2: warm LIF, no stores (u in [ws, start)).
  for (int s = ws + 1; s <= start; ++s) {
    scatter(s);
    float p0, p1; unpack2(aP, p0, p1);
    float z0 = fmaf(p0 + bb0, sc0, sh0);
    v0 = fmaf(z0 - v0, 0.5f, v0);
    if (v0 >= 1.0f) v0 = 0.0f;
    float z1 = fmaf(p1 + bb1, sc1, sh1);
    v1 = fmaf(z1 - v1, 0.5f, v1);
    if (v1 >= 1.0f) v1 = 0.0f;
    rot();
  }
  // Phase 3: LIF + stores (u in [start, end)), flush every 8 steps.
  for (int s = start + 1; s <= end; ++s) {
    scatter(s);
    const int u = s - 1;
    float p0, p1; unpack2(aP, p0, p1);
    float z0 = fmaf(p0 + bb0, sc0, sh0);
    v0 = fmaf(z0 - v0, 0.5f, v0);
    bool s0 = (v0 >= 1.0f);
    float z1 = fmaf(p1 + bb1, sc1, sh1);
    v1 = fmaf(z1 - v1, 0.5f, v1);
    bool s1 = (v1 >= 1.0f);
    ot[warp][o][u & 7]  = s0 ? 1.0f : 0.0f;    // stride-9: conflict-free
    ot[warp][o2][u & 7] = s1 ? 1.0f : 0.0f;
    v0 = s0 ? 0.0f : v0;
    v1 = s1 ? 0.0f : v1;
    rot();
    if ((u & 7) == 7) {                        // warp-uniform flush
      __syncwarp();
      const int col = lane & 7;
      const int tb = u - 7;
#pragma unroll 4
      for (int r = lane >> 3; r < E; r += 4)   // 32B sectors, fully utilized
        out[(size_t)(b * E + r) * T + tb + col] = ot[warp][r][col];
      __syncwarp();
    }
  }
}

// ---------------------------------------------------------------------------
extern "C" void kernel_launch(void* const* d_in, const int* in_sizes, int n_in,
                              void* d_out, int out_size) {
  const float* x   = (const float*)d_in[0];
  const float* w1  = (const float*)d_in[1];
  const float* b1  = (const float*)d_in[2];
  const float* g1  = (const float*)d_in[3];
  const float* be1 = (const float*)d_in[4];
  const float* m1  = (const float*)d_in[5];
  const float* v1  = (const float*)d_in[6];
  const float* w2  = (const float*)d_in[7];
  const float* b2  = (const float*)d_in[8];
  const float* g2  = (const float*)d_in[9];
  const float* be2 = (const float*)d_in[10];
  const float* m2  = (const float*)d_in[11];
  const float* v2  = (const float*)d_in[12];
  float* out = (float*)d_out;

  lif1_kernel<<<dim3(NC1, B), 128>>>(x, w1, b1, g1, be1, m1, v1);
  lif2_kernel<<<dim3(NC2, B), 256>>>(w2, b2, g2, be2, m2, v2, out);
}

// round 14
// speedup vs baseline: 2.1190x; 1.1036x over previous
#include <cuda_runtime.h>
#include <math.h>

// Problem constants (fixed by the reference setup_inputs()).
namespace {
constexpr int T   = 16384;
constexpr int B   = 64;
constexpr int CIN = 8;
constexpr int H   = 32;   // hidden channels (layer 1 out)
constexpr int E   = 64;   // embed channels (layer 2 out)
constexpr int W   = 32;   // LIF warm-up steps: state error <= 2^-32 (0.5x decay
                          //  per step) and exact after any coincident hard reset
constexpr int SUB = 128;  // useful steps per warp (both kernels)

// Kernel A tiling: 4 warps x 128 steps.
constexpr int CH1 = 512;
constexpr int NC1 = T / CH1;       // 32 chunks
constexpr int L1  = CH1 + W + 2;   // 546

// Kernel B tiling: 8 warps x 128 steps (weight tables amortized over 8 warps).
constexpr int CH2 = 1024;
constexpr int NC2 = T / CH2;       // 16 chunks
constexpr int L2  = CH2 + W + 2;   // 1058
}

// Layer-1 spikes as bitmasks: bit c of g_masks[b*T + t] = spike of channel c at t.
__device__ unsigned g_masks[B * T];

typedef unsigned long long ull;

__device__ __forceinline__ ull fma2(ull a, ull b, ull c) {
  ull d; asm("fma.rn.f32x2 %0, %1, %2, %3;" : "=l"(d) : "l"(a), "l"(b), "l"(c));
  return d;
}
__device__ __forceinline__ ull add2(ull a, ull b) {
  ull d; asm("add.rn.f32x2 %0, %1, %2;" : "=l"(d) : "l"(a), "l"(b));
  return d;
}
__device__ __forceinline__ ull pack2(float lo, float hi) {
  ull d; asm("mov.b64 %0, {%1, %2};" : "=l"(d) : "f"(lo), "f"(hi));
  return d;
}
__device__ __forceinline__ void unpack2(ull v, float& lo, float& hi) {
  asm("mov.b64 {%0, %1}, %2;" : "=f"(lo), "=f"(hi) : "l"(v));
}

// ---------------------------------------------------------------------------
// Kernel A: conv1d(8->32,k=3,same) + BN(eval) + LIF  -> spike bitmasks.
// 128-thread block per (batch, 512-chunk); each of 4 warps runs a 128-step
// sub-chunk (+32 warm-up) over a shared x tile. lane = output channel.
// x tile is [t][8ch] so one step = 2x LDS.128 broadcast; conv = 12x fma.f32x2.
// ---------------------------------------------------------------------------
__global__ __launch_bounds__(128, 6) void lif1_kernel(
    const float* __restrict__ x,  const float* __restrict__ w1,
    const float* __restrict__ b1, const float* __restrict__ g1,
    const float* __restrict__ be1, const float* __restrict__ m1,
    const float* __restrict__ v1) {
  __shared__ __align__(16) float xs[L1][CIN];
  const int b    = blockIdx.y;
  const int t0   = blockIdx.x * CH1;
  const int base = t0 - W - 1;      // xs[j] = x[b, :, base+j]
  const int tid  = threadIdx.x;
  const int lane = tid & 31;
  const int warp = tid >> 5;

  // Stage x tile (zero-pad outside [0,T) -> also the conv 'same' pads).
  for (int i = tid; i < CIN * L1; i += 128) {
    int c = i / L1, j = i - c * L1;
    int g = base + j;
    xs[j][c] = (g >= 0 && g < T) ? x[(b * CIN + c) * T + g] : 0.0f;
  }
  __syncthreads();

  // Per-lane packed weights + BN params (unfused BN mirrors reference algebra).
  const float* wp = w1 + lane * (CIN * 3);
  ull wa[4], wb[4], wc[4];
#pragma unroll
  for (int p = 0; p < 4; p++) {
    wa[p] = pack2(wp[(2 * p) * 3 + 0], wp[(2 * p + 1) * 3 + 0]);
    wb[p] = pack2(wp[(2 * p) * 3 + 1], wp[(2 * p + 1) * 3 + 1]);
    wc[p] = pack2(wp[(2 * p) * 3 + 2], wp[(2 * p + 1) * 3 + 2]);
  }
  const float sc = g1[lane] / sqrtf(v1[lane] + 1e-5f);
  const float sh = be1[lane] - m1[lane] * sc;
  const float bb = b1[lane];

  const int start = t0 + warp * SUB;  // this warp's sub-chunk
  const int sw    = start - W;        // warm-up start (negative only for chunk 0)
  float v = 0.0f;
  unsigned keep = 0;
  unsigned* mrow = g_masks + b * T;

  // Rotating packed x windows: A=x(t-1), B=x(t), C<-x(t+1); period-4 rotation.
  ull A[4], Bv[4], C[4], D[4];
  {
    int j = sw - 1 - base;  // = warp*SUB
    const ulonglong2* r = reinterpret_cast<const ulonglong2*>(xs[j]);
    ulonglong2 q0 = r[0], q1 = r[1];
    A[0] = q0.x; A[1] = q0.y; A[2] = q1.x; A[3] = q1.y;
    r  = reinterpret_cast<const ulonglong2*>(xs[j + 1]);
    q0 = r[0]; q1 = r[1];
    Bv[0] = q0.x; Bv[1] = q0.y; Bv[2] = q1.x; Bv[3] = q1.y;
  }

  auto conv = [&](const ull (&P)[4], const ull (&Q)[4], ull (&R)[4],
                  int tt) -> float {
    const int j = tt + 1 - base;
    const ulonglong2* r = reinterpret_cast<const ulonglong2*>(xs[j]);
    ulonglong2 q0 = r[0], q1 = r[1];
    R[0] = q0.x; R[1] = q0.y; R[2] = q1.x; R[3] = q1.y;
    ull a0 = 0, a1 = 0, a2 = 0;   // 0 bits == packed {0.f, 0.f}
#pragma unroll
    for (int p = 0; p < 4; p++) {
      a0 = fma2(wa[p], P[p], a0);
      a1 = fma2(wb[p], Q[p], a1);
      a2 = fma2(wc[p], R[p], a2);
    }
    float lo, hi;
    unpack2(add2(add2(a0, a1), a2), lo, hi);
    return lo + hi;
  };

  auto wstep = [&](const ull (&P)[4], const ull (&Q)[4], ull (&R)[4], int tt) {
    float cv = conv(P, Q, R, tt);
    if (tt >= 0) {                              // chunk 0: true start at t=0
      float z = fmaf(cv + bb, sc, sh);          // (conv + b)*scale + shift
      v = fmaf(z - v, 0.5f, v);                 // v += (x - v)/tau, tau=2
      if (v >= 1.0f) v = 0.0f;                  // hard reset
    }
  };
  auto mstep = [&](const ull (&P)[4], const ull (&Q)[4], ull (&R)[4], int tt) {
    float cv = conv(P, Q, R, tt);
    float z = fmaf(cv + bb, sc, sh);
    v = fmaf(z - v, 0.5f, v);
    bool sp = (v >= 1.0f);
    unsigned mk = __ballot_sync(0xffffffffu, sp);
    if (sp) v = 0.0f;
    if ((tt & 31) == lane) keep = mk;           // distribute masks over lanes
    if ((tt & 31) == 31) mrow[tt - 31 + lane] = keep;  // 128B coalesced store
  };

  // W and SUB are multiples of 4: period-4 rotation, no copies.
  for (int t = sw; t < start; t += 4) {
    wstep(A, Bv, C, t);   wstep(Bv, C, D, t + 1);
    wstep(C, D, A, t + 2); wstep(D, A, Bv, t + 3);
  }
  for (int t = start; t < start + SUB; t += 4) {
    mstep(A, Bv, C, t);   mstep(Bv, C, D, t + 1);
    mstep(C, D, A, t + 2); mstep(D, A, Bv, t + 3);
  }
}

// ---------------------------------------------------------------------------
// Kernel B: sparse conv1d(32->64,k=3) + BN + LIF -> out, SCATTER formulation.
// 256-thread block per (batch, 1024-chunk); 8 warps x 128-step sub-chunks
// (+32 warm-up) share ONE weight table + mask tile. Lane covers outputs
// o=lane, o+32 via PAIR-PACKED weights (LDS.128 + LDS.64 + 3x add.rn.f32x2
// per bit). Output transpose is done with BALLOTS, not smem: each step's 64
// spike bools become 2 ballot words kept by lane (u&31); every 32 steps each
// lane writes out[r][tb+lane] from bit r of its kept words -> 128B-coalesced
// STG rows, zero smem staging traffic.
// ---------------------------------------------------------------------------
__global__ __launch_bounds__(256, 4) void lif2_kernel(
    const float* __restrict__ w2,  const float* __restrict__ b2,
    const float* __restrict__ g2,  const float* __restrict__ be2,
    const float* __restrict__ m2,  const float* __restrict__ v2p,
    float* __restrict__ out) {
  __shared__ __align__(16) float w4[H][32][4];  // [c][ln]: {t2_o,t2_o2,t1_o,t1_o2}
  __shared__ __align__(8)  float w2x[H][32][2]; // [c][ln]: {t0_o,t0_o2}
  __shared__ unsigned ms[L2];
  const int b    = blockIdx.y;
  const int t0   = blockIdx.x * CH2;
  const int base = t0 - W - 1;
  const int tid  = threadIdx.x;
  const int lane = tid & 31;
  const int warp = tid >> 5;

  // Weights: global w2 layout [E][H][3] -> pair-packed smem layout.
  for (int i = tid; i < H * 32; i += 256) {
    int c = i >> 5, ln = i & 31;
    int o = ln, o2 = ln + 32;
    w4[c][ln][0]  = w2[(o  * H + c) * 3 + 2];
    w4[c][ln][1]  = w2[(o2 * H + c) * 3 + 2];
    w4[c][ln][2]  = w2[(o  * H + c) * 3 + 1];
    w4[c][ln][3]  = w2[(o2 * H + c) * 3 + 1];
    w2x[c][ln][0] = w2[(o  * H + c) * 3 + 0];
    w2x[c][ln][1] = w2[(o2 * H + c) * 3 + 0];
  }
  const unsigned* mrow = g_masks + b * T;
  for (int i = tid; i < L2; i += 256) {
    int g = base + i;
    ms[i] = (g >= 0 && g < T) ? mrow[g] : 0u;  // zero pad = conv 'same' pad
  }
  const int o = lane, o2 = lane + 32;
  const float sc0 = g2[o]  / sqrtf(v2p[o]  + 1e-5f);
  const float sh0 = be2[o]  - m2[o]  * sc0;
  const float bb0 = b2[o];
  const float sc1 = g2[o2] / sqrtf(v2p[o2] + 1e-5f);
  const float sh1 = be2[o2] - m2[o2] * sc1;
  const float bb1 = b2[o2];
  __syncthreads();

  const int start = t0 + warp * SUB;
  const int end   = start + SUB;
  const int sw    = start - W;
  const int ws    = (sw < 0) ? 0 : sw;   // first LIF-active time

  ull aP = 0, aC = 0, aN = 0;            // packed (o, o2) rolling accumulators
  float v0 = 0.f, v1 = 0.f;

  auto scatter = [&](int s) {
    unsigned m = ms[s - base];
    while (m) {                          // warp-uniform mask -> no divergence
      int c = __ffs((int)m) - 1;
      m &= m - 1;
      ulonglong2 wv = *reinterpret_cast<const ulonglong2*>(&w4[c][lane][0]);
      aP = add2(aP, wv.x);               // tap2 pair -> conv(s-1)
      aC = add2(aC, wv.y);               // tap1 pair -> conv(s)
      aN = add2(aN, *reinterpret_cast<const ull*>(&w2x[c][lane][0]));
    }
  };
  auto rot = [&] { aP = aC; aC = aN; aN = 0; };

  // Phase 1: scatter only (u = s-1 < ws; no LIF yet).
  for (int s = sw - 1; s <= ws; ++s) { scatter(s); rot(); }
  // Phase 2: warm LIF, no stores (u in [ws, start)).
  for (int s = ws + 1; s <= start; ++s) {
    scatter(s);
    float p0, p1; unpack2(aP, p0, p1);
    float z0 = fmaf(p0 + bb0, sc0, sh0);
    v0 = fmaf(z0 - v0, 0.5f, v0);
    if (v0 >= 1.0f) v0 = 0.0f;
    float z1 = fmaf(p1 + bb1, sc1, sh1);
    v1 = fmaf(z1 - v1, 0.5f, v1);
    if (v1 >= 1.0f) v1 = 0.0f;
    rot();
  }
  // Phase 3: LIF + ballot-transposed output (u in [start, end)).
  unsigned keep0 = 0, keep1 = 0;
  for (int s = start + 1; s <= end; ++s) {
    scatter(s);
    const int u = s - 1;
    float p0, p1; unpack2(aP, p0, p1);
    float z0 = fmaf(p0 + bb0, sc0, sh0);
    v0 = fmaf(z0 - v0, 0.5f, v0);
    bool s0 = (v0 >= 1.0f);
    float z1 = fmaf(p1 + bb1, sc1, sh1);
    v1 = fmaf(z1 - v1, 0.5f, v1);
    bool s1 = (v1 >= 1.0f);
    unsigned bal0 = __ballot_sync(0xffffffffu, s0);  // bit r = output r
    unsigned bal1 = __ballot_sync(0xffffffffu, s1);  // bit r = output r+32
    v0 = s0 ? 0.0f : v0;
    v1 = s1 ? 0.0f : v1;
    rot();
    if ((u & 31) == lane) { keep0 = bal0; keep1 = bal1; }
    if ((u & 31) == 31) {                // lane l holds step tb+l's 64 spikes
      const int tb = u - 31;
      float* op = out + (size_t)b * E * T + tb + lane;
#pragma unroll 8
      for (int r = 0; r < 32; ++r)       // 128B coalesced row per STG
        op[(size_t)r * T] = ((keep0 >> r) & 1u) ? 1.0f : 0.0f;
#pragma unroll 8
      for (int r = 0; r < 32; ++r)
        op[(size_t)(r + 32) * T] = ((keep1 >> r) & 1u) ? 1.0f : 0.0f;
    }
  }
}

// ---------------------------------------------------------------------------
extern "C" void kernel_launch(void* const* d_in, const int* in_sizes, int n_in,
                              void* d_out, int out_size) {
  const float* x   = (const float*)d_in[0];
  const float* w1  = (const float*)d_in[1];
  const float* b1  = (const float*)d_in[2];
  const float* g1  = (const float*)d_in[3];
  const float* be1 = (const float*)d_in[4];
  const float* m1  = (const float*)d_in[5];
  const float* v1  = (const float*)d_in[6];
  const float* w2  = (const float*)d_in[7];
  const float* b2  = (const float*)d_in[8];
  const float* g2  = (const float*)d_in[9];
  const float* be2 = (const float*)d_in[10];
  const float* m2  = (const float*)d_in[11];
  const float* v2  = (const float*)d_in[12];
  float* out = (float*)d_out;

  lif1_kernel<<<dim3(NC1, B), 128>>>(x, w1, b1, g1, be1, m1, v1);
  lif2_kernel<<<dim3(NC2, B), 256>>>(w2, b2, g2, be2, m2, v2, out);
}

// round 16
// speedup vs baseline: 2.1896x; 1.0333x over previous
#include <cuda_runtime.h>
#include <math.h>

// Problem constants (fixed by the reference setup_inputs()).
namespace {
constexpr int T   = 16384;
constexpr int B   = 64;
constexpr int CIN = 8;
constexpr int H   = 32;   // hidden channels (layer 1 out)
constexpr int E   = 64;   // embed channels (layer 2 out)
constexpr int W   = 32;   // LIF warm-up steps: state error <= 2^-32 (0.5x decay
                          //  per step) and exact after any coincident hard reset
constexpr int SUB = 128;  // useful steps per warp (both kernels)

// Kernel A tiling: 4 warps x 128 steps.
constexpr int CH1 = 512;
constexpr int NC1 = T / CH1;       // 32 chunks
constexpr int L1  = CH1 + W + 2;   // 546

// Kernel B tiling: 8 warps x 128 steps (weight tables amortized over 8 warps).
constexpr int CH2 = 1024;
constexpr int NC2 = T / CH2;       // 16 chunks
constexpr int L2  = CH2 + W + 2;   // 1058
}

// Layer-1 spikes as bitmasks: bit c of g_masks[b*T + t] = spike of channel c at t.
__device__ unsigned g_masks[B * T];

typedef unsigned long long ull;

__device__ __forceinline__ ull fma2(ull a, ull b, ull c) {
  ull d; asm("fma.rn.f32x2 %0, %1, %2, %3;" : "=l"(d) : "l"(a), "l"(b), "l"(c));
  return d;
}
__device__ __forceinline__ ull add2(ull a, ull b) {
  ull d; asm("add.rn.f32x2 %0, %1, %2;" : "=l"(d) : "l"(a), "l"(b));
  return d;
}
__device__ __forceinline__ ull pack2(float lo, float hi) {
  ull d; asm("mov.b64 %0, {%1, %2};" : "=l"(d) : "f"(lo), "f"(hi));
  return d;
}
__device__ __forceinline__ void unpack2(ull v, float& lo, float& hi) {
  asm("mov.b64 {%0, %1}, %2;" : "=f"(lo), "=f"(hi) : "l"(v));
}

// ---------------------------------------------------------------------------
// Kernel A: conv1d(8->32,k=3,same) + BN(eval) + LIF  -> spike bitmasks.
// 128-thread block per (batch, 512-chunk); each of 4 warps runs a 128-step
// sub-chunk (+32 warm-up) over a shared x tile. lane = output channel.
// x tile is [t][8ch] so one step = 2x LDS.128 broadcast; conv = 12x fma.f32x2.
// NOTE: no minBlocks clamp — letting regs float avoids local-memory spills
// in the hot loop (the spill hypothesis for lif1's issue-rate anomaly).
// ---------------------------------------------------------------------------
__global__ __launch_bounds__(128) void lif1_kernel(
    const float* __restrict__ x,  const float* __restrict__ w1,
    const float* __restrict__ b1, const float* __restrict__ g1,
    const float* __restrict__ be1, const float* __restrict__ m1,
    const float* __restrict__ v1) {
  __shared__ __align__(16) float xs[L1][CIN];
  const int b    = blockIdx.y;
  const int t0   = blockIdx.x * CH1;
  const int base = t0 - W - 1;      // xs[j] = x[b, :, base+j]
  const int tid  = threadIdx.x;
  const int lane = tid & 31;
  const int warp = tid >> 5;

  // Stage x tile (zero-pad outside [0,T) -> also the conv 'same' pads).
  for (int i = tid; i < CIN * L1; i += 128) {
    int c = i / L1, j = i - c * L1;
    int g = base + j;
    xs[j][c] = (g >= 0 && g < T) ? x[(b * CIN + c) * T + g] : 0.0f;
  }
  __syncthreads();

  // Per-lane packed weights + BN params (unfused BN mirrors reference algebra).
  const float* wp = w1 + lane * (CIN * 3);
  ull wa[4], wb[4], wc[4];
#pragma unroll
  for (int p = 0; p < 4; p++) {
    wa[p] = pack2(wp[(2 * p) * 3 + 0], wp[(2 * p + 1) * 3 + 0]);
    wb[p] = pack2(wp[(2 * p) * 3 + 1], wp[(2 * p + 1) * 3 + 1]);
    wc[p] = pack2(wp[(2 * p) * 3 + 2], wp[(2 * p + 1) * 3 + 2]);
  }
  const float sc = g1[lane] / sqrtf(v1[lane] + 1e-5f);
  const float sh = be1[lane] - m1[lane] * sc;
  const float bb = b1[lane];

  const int start = t0 + warp * SUB;  // this warp's sub-chunk
  const int sw    = start - W;        // warm-up start (negative only for chunk 0)
  float v = 0.0f;
  unsigned keep = 0;
  unsigned* mrow = g_masks + b * T;

  // Rotating packed x windows: A=x(t-1), B=x(t), C<-x(t+1); period-4 rotation.
  ull A[4], Bv[4], C[4], D[4];
  {
    int j = sw - 1 - base;  // = warp*SUB
    const ulonglong2* r = reinterpret_cast<const ulonglong2*>(xs[j]);
    ulonglong2 q0 = r[0], q1 = r[1];
    A[0] = q0.x; A[1] = q0.y; A[2] = q1.x; A[3] = q1.y;
    r  = reinterpret_cast<const ulonglong2*>(xs[j + 1]);
    q0 = r[0]; q1 = r[1];
    Bv[0] = q0.x; Bv[1] = q0.y; Bv[2] = q1.x; Bv[3] = q1.y;
  }

  auto conv = [&](const ull (&P)[4], const ull (&Q)[4], ull (&R)[4],
                  int tt) -> float {
    const int j = tt + 1 - base;
    const ulonglong2* r = reinterpret_cast<const ulonglong2*>(xs[j]);
    ulonglong2 q0 = r[0], q1 = r[1];
    R[0] = q0.x; R[1] = q0.y; R[2] = q1.x; R[3] = q1.y;
    ull a0 = 0, a1 = 0, a2 = 0;   // 0 bits == packed {0.f, 0.f}
#pragma unroll
    for (int p = 0; p < 4; p++) {
      a0 = fma2(wa[p], P[p], a0);
      a1 = fma2(wb[p], Q[p], a1);
      a2 = fma2(wc[p], R[p], a2);
    }
    float lo, hi;
    unpack2(add2(add2(a0, a1), a2), lo, hi);
    return lo + hi;
  };

  auto wstep = [&](const ull (&P)[4], const ull (&Q)[4], ull (&R)[4], int tt) {
    float cv = conv(P, Q, R, tt);
    if (tt >= 0) {                              // chunk 0: true start at t=0
      float z = fmaf(cv + bb, sc, sh);          // (conv + b)*scale + shift
      v = fmaf(z - v, 0.5f, v);                 // v += (x - v)/tau, tau=2
      if (v >= 1.0f) v = 0.0f;                  // hard reset
    }
  };
  auto mstep = [&](const ull (&P)[4], const ull (&Q)[4], ull (&R)[4], int tt) {
    float cv = conv(P, Q, R, tt);
    float z = fmaf(cv + bb, sc, sh);
    v = fmaf(z - v, 0.5f, v);
    bool sp = (v >= 1.0f);
    unsigned mk = __ballot_sync(0xffffffffu, sp);
    if (sp) v = 0.0f;
    if ((tt & 31) == lane) keep = mk;           // distribute masks over lanes
    if ((tt & 31) == 31) mrow[tt - 31 + lane] = keep;  // 128B coalesced store
  };

  // W and SUB are multiples of 4: period-4 rotation, no copies.
  for (int t = sw; t < start; t += 4) {
    wstep(A, Bv, C, t);   wstep(Bv, C, D, t + 1);
    wstep(C, D, A, t + 2); wstep(D, A, Bv, t + 3);
  }
  for (int t = start; t < start + SUB; t += 4) {
    mstep(A, Bv, C, t);   mstep(Bv, C, D, t + 1);
    mstep(C, D, A, t + 2); mstep(D, A, Bv, t + 3);
  }
}

// ---------------------------------------------------------------------------
// Kernel B: sparse conv1d(32->64,k=3) + BN + LIF -> out, SCATTER formulation.
// 256-thread block per (batch, 1024-chunk); 8 warps x 128-step sub-chunks
// (+32 warm-up) share ONE weight table + mask tile. Lane covers outputs
// o=lane, o+32 via PAIR-PACKED weights (LDS.128 + LDS.64 + 3x add.rn.f32x2
// per bit). LIF recurrence is PACKED f32x2 for both outputs (bit-identical
// per component: fma2(v,-1,z) == fl(z-v)). Output transpose via BALLOTS:
// each step's 64 spike bools -> 2 ballot words kept by lane (u&31); every 32
// steps each lane writes out[r][tb+lane] -> 128B-coalesced STG rows.
// ---------------------------------------------------------------------------
__global__ __launch_bounds__(256, 4) void lif2_kernel(
    const float* __restrict__ w2,  const float* __restrict__ b2,
    const float* __restrict__ g2,  const float* __restrict__ be2,
    const float* __restrict__ m2,  const float* __restrict__ v2p,
    float* __restrict__ out) {
  __shared__ __align__(16) float w4[H][32][4];  // [c][ln]: {t2_o,t2_o2,t1_o,t1_o2}
  __shared__ __align__(8)  float w2x[H][32][2]; // [c][ln]: {t0_o,t0_o2}
  __shared__ unsigned ms[L2];
  const int b    = blockIdx.y;
  const int t0   = blockIdx.x * CH2;
  const int base = t0 - W - 1;
  const int tid  = threadIdx.x;
  const int lane = tid & 31;
  const int warp = tid >> 5;

  // Weights: global w2 layout [E][H][3] -> pair-packed smem layout.
  for (int i = tid; i < H * 32; i += 256) {
    int c = i >> 5, ln = i & 31;
    int o = ln, o2 = ln + 32;
    w4[c][ln][0]  = w2[(o  * H + c) * 3 + 2];
    w4[c][ln][1]  = w2[(o2 * H + c) * 3 + 2];
    w4[c][ln][2]  = w2[(o  * H + c) * 3 + 1];
    w4[c][ln][3]  = w2[(o2 * H + c) * 3 + 1];
    w2x[c][ln][0] = w2[(o  * H + c) * 3 + 0];
    w2x[c][ln][1] = w2[(o2 * H + c) * 3 + 0];
  }
  const unsigned* mrow = g_masks + b * T;
  for (int i = tid; i < L2; i += 256) {
    int g = base + i;
    ms[i] = (g >= 0 && g < T) ? mrow[g] : 0u;  // zero pad = conv 'same' pad
  }
  const int o = lane, o2 = lane + 32;
  const float sc0 = g2[o]  / sqrtf(v2p[o]  + 1e-5f);
  const float sh0 = be2[o]  - m2[o]  * sc0;
  const float sc1 = g2[o2] / sqrtf(v2p[o2] + 1e-5f);
  const float sh1 = be2[o2] - m2[o2] * sc1;
  const ull bb01 = pack2(b2[o], b2[o2]);
  const ull sc01 = pack2(sc0, sc1);
  const ull sh01 = pack2(sh0, sh1);
  const ull hf01 = pack2(0.5f, 0.5f);
  const ull ng01 = pack2(-1.0f, -1.0f);
  __syncthreads();

  const int start = t0 + warp * SUB;
  const int end   = start + SUB;
  const int sw    = start - W;
  const int ws    = (sw < 0) ? 0 : sw;   // first LIF-active time

  ull aP = 0, aC = 0, aN = 0;            // packed (o, o2) rolling accumulators
  ull vv = 0;                            // packed LIF state {v0, v1}

  auto scatter = [&](int s) {
    unsigned m = ms[s - base];
    while (m) {                          // warp-uniform mask -> no divergence
      int c = __ffs((int)m) - 1;
      m &= m - 1;
      ulonglong2 wv = *reinterpret_cast<const ulonglong2*>(&w4[c][lane][0]);
      aP = add2(aP, wv.x);               // tap2 pair -> conv(s-1)
      aC = add2(aC, wv.y);               // tap1 pair -> conv(s)
      aN = add2(aN, *reinterpret_cast<const ull*>(&w2x[c][lane][0]));
    }
  };
  auto rot = [&] { aP = aC; aC = aN; aN = 0; };

  // Phase 1: scatter only (u = s-1 < ws; no LIF yet).
  for (int s = sw - 1; s <= ws; ++s) { scatter(s); rot(); }
  // Phase 2: warm LIF, no stores (u in [ws, start)).
  for (int s = ws + 1; s <= start; ++s) {
    scatter(s);
    ull zp = fma2(add2(aP, bb01), sc01, sh01);   // z = (conv+b)*scale+shift
    ull dp = fma2(vv, ng01, zp);                  // d = z - v (exact FADD equiv)
    vv = fma2(dp, hf01, vv);                      // v += d * 0.5
    float v0, v1; unpack2(vv, v0, v1);
    v0 = (v0 >= 1.0f) ? 0.0f : v0;                // hard reset
    v1 = (v1 >= 1.0f) ? 0.0f : v1;
    vv = pack2(v0, v1);
    rot();
  }
  // Phase 3: LIF + ballot-transposed output (u in [start, end)).
  unsigned keep0 = 0, keep1 = 0;
  for (int s = start + 1; s <= end; ++s) {
    scatter(s);
    const int u = s - 1;
    ull zp = fma2(add2(aP, bb01), sc01, sh01);
    ull dp = fma2(vv, ng01, zp);
    vv = fma2(dp, hf01, vv);
    float v0, v1; unpack2(vv, v0, v1);
    bool s0 = (v0 >= 1.0f);
    bool s1 = (v1 >= 1.0f);
    unsigned bal0 = __ballot_sync(0xffffffffu, s0);  // bit r = output r
    unsigned bal1 = __ballot_sync(0xffffffffu, s1);  // bit r = output r+32
    v0 = s0 ? 0.0f : v0;
    v1 = s1 ? 0.0f : v1;
    vv = pack2(v0, v1);
    rot();
    if ((u & 31) == lane) { keep0 = bal0; keep1 = bal1; }
    if ((u & 31) == 31) {                // lane l holds step tb+l's 64 spikes
      const int tb = u - 31;
      float* op = out + (size_t)b * E * T + tb + lane;
#pragma unroll 8
      for (int r = 0; r < 32; ++r)       // 128B coalesced row per STG
        op[(size_t)r * T] = ((keep0 >> r) & 1u) ? 1.0f : 0.0f;
#pragma unroll 8
      for (int r = 0; r < 32; ++r)
        op[(size_t)(r + 32) * T] = ((keep1 >> r) & 1u) ? 1.0f : 0.0f;
    }
  }
}

// ---------------------------------------------------------------------------
extern "C" void kernel_launch(void* const* d_in, const int* in_sizes, int n_in,
                              void* d_out, int out_size) {
  const float* x   = (const float*)d_in[0];
  const float* w1  = (const float*)d_in[1];
  const float* b1  = (const float*)d_in[2];
  const float* g1  = (const float*)d_in[3];
  const float* be1 = (const float*)d_in[4];
  const float* m1  = (const float*)d_in[5];
  const float* v1  = (const float*)d_in[6];
  const float* w2  = (const float*)d_in[7];
  const float* b2  = (const float*)d_in[8];
  const float* g2  = (const float*)d_in[9];
  const float* be2 = (const float*)d_in[10];
  const float* m2  = (const float*)d_in[11];
  const float* v2  = (const float*)d_in[12];
  float* out = (float*)d_out;

  lif1_kernel<<<dim3(NC1, B), 128>>>(x, w1, b1, g1, be1, m1, v1);
  lif2_kernel<<<dim3(NC2, B), 256>>>(w2, b2, g2, be2, m2, v2, out);
}

// round 17
// speedup vs baseline: 2.1928x; 1.0014x over previous
#include <cuda_runtime.h>
#include <math.h>

// Problem constants (fixed by the reference setup_inputs()).
namespace {
constexpr int T   = 16384;
constexpr int B   = 64;
constexpr int CIN = 8;
constexpr int H   = 32;   // hidden channels (layer 1 out)
constexpr int E   = 64;   // embed channels (layer 2 out)
constexpr int W   = 32;   // LIF warm-up steps: state error <= 2^-32 (0.5x decay
                          //  per step) and exact after any coincident hard reset
constexpr int SUB = 256;  // useful steps per warp (warm-up overhead 12.5%)

// Both kernels: 4 warps x 256 steps per 1024-step chunk.
constexpr int CH  = 1024;
constexpr int NC  = T / CH;      // 16 chunks
constexpr int L   = CH + W + 2;  // 1058
}

// Layer-1 spikes as bitmasks: bit c of g_masks[b*T + t] = spike of channel c at t.
__device__ unsigned g_masks[B * T];

typedef unsigned long long ull;

__device__ __forceinline__ ull fma2(ull a, ull b, ull c) {
  ull d; asm("fma.rn.f32x2 %0, %1, %2, %3;" : "=l"(d) : "l"(a), "l"(b), "l"(c));
  return d;
}
__device__ __forceinline__ ull add2(ull a, ull b) {
  ull d; asm("add.rn.f32x2 %0, %1, %2;" : "=l"(d) : "l"(a), "l"(b));
  return d;
}
__device__ __forceinline__ ull pack2(float lo, float hi) {
  ull d; asm("mov.b64 %0, {%1, %2};" : "=l"(d) : "f"(lo), "f"(hi));
  return d;
}
__device__ __forceinline__ void unpack2(ull v, float& lo, float& hi) {
  asm("mov.b64 {%0, %1}, %2;" : "=f"(lo), "=f"(hi) : "l"(v));
}

// ---------------------------------------------------------------------------
// Kernel A: conv1d(8->32,k=3,same) + BN(eval) + LIF  -> spike bitmasks.
// 128-thread block per (batch, 1024-chunk); each of 4 warps runs a 256-step
// sub-chunk (+32 warm-up) over a shared x tile. lane = output channel.
// x tile is [t][8ch] so one step = 2x LDS.128 broadcast; conv = 12x fma.f32x2.
// ---------------------------------------------------------------------------
__global__ __launch_bounds__(128) void lif1_kernel(
    const float* __restrict__ x,  const float* __restrict__ w1,
    const float* __restrict__ b1, const float* __restrict__ g1,
    const float* __restrict__ be1, const float* __restrict__ m1,
    const float* __restrict__ v1) {
  __shared__ __align__(16) float xs[L][CIN];
  const int b    = blockIdx.y;
  const int t0   = blockIdx.x * CH;
  const int base = t0 - W - 1;      // xs[j] = x[b, :, base+j]
  const int tid  = threadIdx.x;
  const int lane = tid & 31;
  const int warp = tid >> 5;

  // Stage x tile (zero-pad outside [0,T) -> also the conv 'same' pads).
  for (int i = tid; i < CIN * L; i += 128) {
    int c = i / L, j = i - c * L;
    int g = base + j;
    xs[j][c] = (g >= 0 && g < T) ? x[(b * CIN + c) * T + g] : 0.0f;
  }
  __syncthreads();

  // Per-lane packed weights + BN params (unfused BN mirrors reference algebra).
  const float* wp = w1 + lane * (CIN * 3);
  ull wa[4], wb[4], wc[4];
#pragma unroll
  for (int p = 0; p < 4; p++) {
    wa[p] = pack2(wp[(2 * p) * 3 + 0], wp[(2 * p + 1) * 3 + 0]);
    wb[p] = pack2(wp[(2 * p) * 3 + 1], wp[(2 * p + 1) * 3 + 1]);
    wc[p] = pack2(wp[(2 * p) * 3 + 2], wp[(2 * p + 1) * 3 + 2]);
  }
  const float sc = g1[lane] / sqrtf(v1[lane] + 1e-5f);
  const float sh = be1[lane] - m1[lane] * sc;
  const float bb = b1[lane];

  const int start = t0 + warp * SUB;  // this warp's sub-chunk
  const int sw    = start - W;        // warm-up start (negative only for chunk 0)
  float v = 0.0f;
  unsigned keep = 0;
  unsigned* mrow = g_masks + b * T;

  // Rotating packed x windows: A=x(t-1), B=x(t), C<-x(t+1); period-4 rotation.
  ull A[4], Bv[4], C[4], D[4];
  {
    int j = sw - 1 - base;  // = warp*SUB
    const ulonglong2* r = reinterpret_cast<const ulonglong2*>(xs[j]);
    ulonglong2 q0 = r[0], q1 = r[1];
    A[0] = q0.x; A[1] = q0.y; A[2] = q1.x; A[3] = q1.y;
    r  = reinterpret_cast<const ulonglong2*>(xs[j + 1]);
    q0 = r[0]; q1 = r[1];
    Bv[0] = q0.x; Bv[1] = q0.y; Bv[2] = q1.x; Bv[3] = q1.y;
  }

  auto conv = [&](const ull (&P)[4], const ull (&Q)[4], ull (&R)[4],
                  int tt) -> float {
    const int j = tt + 1 - base;
    const ulonglong2* r = reinterpret_cast<const ulonglong2*>(xs[j]);
    ulonglong2 q0 = r[0], q1 = r[1];
    R[0] = q0.x; R[1] = q0.y; R[2] = q1.x; R[3] = q1.y;
    ull a0 = 0, a1 = 0, a2 = 0;   // 0 bits == packed {0.f, 0.f}
#pragma unroll
    for (int p = 0; p < 4; p++) {
      a0 = fma2(wa[p], P[p], a0);
      a1 = fma2(wb[p], Q[p], a1);
      a2 = fma2(wc[p], R[p], a2);
    }
    float lo, hi;
    unpack2(add2(add2(a0, a1), a2), lo, hi);
    return lo + hi;
  };

  auto wstep = [&](const ull (&P)[4], const ull (&Q)[4], ull (&R)[4], int tt) {
    float cv = conv(P, Q, R, tt);
    if (tt >= 0) {                              // chunk 0: true start at t=0
      float z = fmaf(cv + bb, sc, sh);          // (conv + b)*scale + shift
      v = fmaf(z - v, 0.5f, v);                 // v += (x - v)/tau, tau=2
      if (v >= 1.0f) v = 0.0f;                  // hard reset
    }
  };
  auto mstep = [&](const ull (&P)[4], const ull (&Q)[4], ull (&R)[4], int tt) {
    float cv = conv(P, Q, R, tt);
    float z = fmaf(cv + bb, sc, sh);
    v = fmaf(z - v, 0.5f, v);
    bool sp = (v >= 1.0f);
    unsigned mk = __ballot_sync(0xffffffffu, sp);
    if (sp) v = 0.0f;
    if ((tt & 31) == lane) keep = mk;           // distribute masks over lanes
    if ((tt & 31) == 31) mrow[tt - 31 + lane] = keep;  // 128B coalesced store
  };

  // W and SUB are multiples of 4: period-4 rotation, no copies.
  for (int t = sw; t < start; t += 4) {
    wstep(A, Bv, C, t);   wstep(Bv, C, D, t + 1);
    wstep(C, D, A, t + 2); wstep(D, A, Bv, t + 3);
  }
  for (int t = start; t < start + SUB; t += 4) {
    mstep(A, Bv, C, t);   mstep(Bv, C, D, t + 1);
    mstep(C, D, A, t + 2); mstep(D, A, Bv, t + 3);
  }
}

// ---------------------------------------------------------------------------
// Kernel B: sparse conv1d(32->64,k=3) + BN + LIF -> out, SCATTER formulation.
// 128-thread block per (batch, 1024-chunk); 4 warps x 256-step sub-chunks
// (+32 warm-up) share ONE weight table + mask tile. Lane covers outputs
// o=lane, o+32 via PAIR-PACKED weights (LDS.128 + LDS.64 + 3x add.rn.f32x2
// per bit). LIF recurrence is PACKED f32x2 (bit-identical per component).
// Output transpose via BALLOTS: 2 ballot words/step kept by lane (u&31);
// every 32 steps each lane writes out[r][tb+lane] -> 128B-coalesced STG rows.
// Small smem (~28.5KB) -> 7-8 blocks/SM -> grid 1024 fits in ONE wave.
// ---------------------------------------------------------------------------
__global__ __launch_bounds__(128, 8) void lif2_kernel(
    const float* __restrict__ w2,  const float* __restrict__ b2,
    const float* __restrict__ g2,  const float* __restrict__ be2,
    const float* __restrict__ m2,  const float* __restrict__ v2p,
    float* __restrict__ out) {
  __shared__ __align__(16) float w4[H][32][4];  // [c][ln]: {t2_o,t2_o2,t1_o,t1_o2}
  __shared__ __align__(8)  float w2x[H][32][2]; // [c][ln]: {t0_o,t0_o2}
  __shared__ unsigned ms[L];
  const int b    = blockIdx.y;
  const int t0   = blockIdx.x * CH;
  const int base = t0 - W - 1;
  const int tid  = threadIdx.x;
  const int lane = tid & 31;
  const int warp = tid >> 5;

  // Weights: global w2 layout [E][H][3] -> pair-packed smem layout.
  for (int i = tid; i < H * 32; i += 128) {
    int c = i >> 5, ln = i & 31;
    int o = ln, o2 = ln + 32;
    w4[c][ln][0]  = w2[(o  * H + c) * 3 + 2];
    w4[c][ln][1]  = w2[(o2 * H + c) * 3 + 2];
    w4[c][ln][2]  = w2[(o  * H + c) * 3 + 1];
    w4[c][ln][3]  = w2[(o2 * H + c) * 3 + 1];
    w2x[c][ln][0] = w2[(o  * H + c) * 3 + 0];
    w2x[c][ln][1] = w2[(o2 * H + c) * 3 + 0];
  }
  const unsigned* mrow = g_masks + b * T;
  for (int i = tid; i < L; i += 128) {
    int g = base + i;
    ms[i] = (g >= 0 && g < T) ? mrow[g] : 0u;  // zero pad = conv 'same' pad
  }
  const int o = lane, o2 = lane + 32;
  const float sc0 = g2[o]  / sqrtf(v2p[o]  + 1e-5f);
  const float sh0 = be2[o]  - m2[o]  * sc0;
  const float sc1 = g2[o2] / sqrtf(v2p[o2] + 1e-5f);
  const float sh1 = be2[o2] - m2[o2] * sc1;
  const ull bb01 = pack2(b2[o], b2[o2]);
  const ull sc01 = pack2(sc0, sc1);
  const ull sh01 = pack2(sh0, sh1);
  const ull hf01 = pack2(0.5f, 0.5f);
  const ull ng01 = pack2(-1.0f, -1.0f);
  __syncthreads();

  const int start = t0 + warp * SUB;
  const int end   = start + SUB;
  const int sw    = start - W;
  const int ws    = (sw < 0) ? 0 : sw;   // first LIF-active time

  ull aP = 0, aC = 0, aN = 0;            // packed (o, o2) rolling accumulators
  ull vv = 0;                            // packed LIF state {v0, v1}

  auto scatter = [&](int s) {
    unsigned m = ms[s - base];
    while (m) {                          // warp-uniform mask -> no divergence
      int c = __ffs((int)m) - 1;
      m &= m - 1;
      ulonglong2 wv = *reinterpret_cast<const ulonglong2*>(&w4[c][lane][0]);
      aP = add2(aP, wv.x);               // tap2 pair -> conv(s-1)
      aC = add2(aC, wv.y);               // tap1 pair -> conv(s)
      aN = add2(aN, *reinterpret_cast<const ull*>(&w2x[c][lane][0]));
    }
  };
  auto rot = [&] { aP = aC; aC = aN; aN = 0; };

  // Phase 1: scatter only (u = s-1 < ws; no LIF yet).
  for (int s = sw - 1; s <= ws; ++s) { scatter(s); rot(); }
  // Phase 2: warm LIF, no stores (u in [ws, start)).
  for (int s = ws + 1; s <= start; ++s) {
    scatter(s);
    ull zp = fma2(add2(aP, bb01), sc01, sh01);   // z = (conv+b)*scale+shift
    ull dp = fma2(vv, ng01, zp);                  // d = z - v (exact FADD equiv)
    vv = fma2(dp, hf01, vv);                      // v += d * 0.5
    float v0, v1; unpack2(vv, v0, v1);
    v0 = (v0 >= 1.0f) ? 0.0f : v0;                // hard reset
    v1 = (v1 >= 1.0f) ? 0.0f : v1;
    vv = pack2(v0, v1);
    rot();
  }
  // Phase 3: LIF + ballot-transposed output (u in [start, end)).
  unsigned keep0 = 0, keep1 = 0;
  for (int s = start + 1; s <= end; ++s) {
    scatter(s);
    const int u = s - 1;
    ull zp = fma2(add2(aP, bb01), sc01, sh01);
    ull dp = fma2(vv, ng01, zp);
    vv = fma2(dp, hf01, vv);
    float v0, v1; unpack2(vv, v0, v1);
    bool s0 = (v0 >= 1.0f);
    bool s1 = (v1 >= 1.0f);
    unsigned bal0 = __ballot_sync(0xffffffffu, s0);  // bit r = output r
    unsigned bal1 = __ballot_sync(0xffffffffu, s1);  // bit r = output r+32
    v0 = s0 ? 0.0f : v0;
    v1 = s1 ? 0.0f : v1;
    vv = pack2(v0, v1);
    rot();
    if ((u & 31) == lane) { keep0 = bal0; keep1 = bal1; }
    if ((u & 31) == 31) {                // lane l holds step tb+l's 64 spikes
      const int tb = u - 31;
      float* op = out + (size_t)b * E * T + tb + lane;
#pragma unroll 8
      for (int r = 0; r < 32; ++r)       // 128B coalesced row per STG
        op[(size_t)r * T] = ((keep0 >> r) & 1u) ? 1.0f : 0.0f;
#pragma unroll 8
      for (int r = 0; r < 32; ++r)
        op[(size_t)(r + 32) * T] = ((keep1 >> r) & 1u) ? 1.0f : 0.0f;
    }
  }
}

// ---------------------------------------------------------------------------
extern "C" void kernel_launch(void* const* d_in, const int* in_sizes, int n_in,
                              void* d_out, int out_size) {
  const float* x   = (const float*)d_in[0];
  const float* w1  = (const float*)d_in[1];
  const float* b1  = (const float*)d_in[2];
  const float* g1  = (const float*)d_in[3];
  const float* be1 = (const float*)d_in[4];
  const float* m1  = (const float*)d_in[5];
  const float* v1  = (const float*)d_in[6];
  const float* w2  = (const float*)d_in[7];
  const float* b2  = (const float*)d_in[8];
  const float* g2  = (const float*)d_in[9];
  const float* be2 = (const float*)d_in[10];
  const float* m2  = (const float*)d_in[11];
  const float* v2  = (const float*)d_in[12];
  float* out = (float*)d_out;

  lif1_kernel<<<dim3(NC, B), 128>>>(x, w1, b1, g1, be1, m1, v1);
  lif2_kernel<<<dim3(NC, B), 128>>>(w2, b2, g2, be2, m2, v2, out);
}